// round 8
// baseline (speedup 1.0000x reference)
#include <cuda_runtime.h>
#include <math.h>

// Problem constants (fixed by the dataset)
#define NE 4096
#define NW 8192
#define KD 128
#define GG 1024
#define MM 64
#define JJ 256

#define NBLK 1184   // 148 SMs * 8 blocks (streaming kernel)
#define NTHR 256
#define NTILES 1024 // (8192/32)*(128/32) transpose tiles == GG

// Scratch (device globals — no runtime allocation allowed)
__device__ float g_Wt[NW * KD];    // transposed W (4 MB)
__device__ float g_pwt[NTILES];    // per-tile relu(W)^2 partials (from prep)
__device__ float g_pr[NBLK];
__device__ float g_pe[NBLK];
__device__ float g_sim[GG];
__device__ float g_ent[2];
__device__ int   g_tbar = 0;       // transpose-done counter (reset by K2 compose)
__device__ int   g_done = 0;       // K2 completion ticket  (reset by K2 compose)

__device__ __forceinline__ float block_reduce(float v) {
    __shared__ float sh[32];
    int lane = threadIdx.x & 31;
    int wid  = threadIdx.x >> 5;
    #pragma unroll
    for (int o = 16; o > 0; o >>= 1) v += __shfl_down_sync(0xffffffffu, v, o);
    __syncthreads();
    if (lane == 0) sh[wid] = v;
    __syncthreads();
    v = (threadIdx.x < (NTHR >> 5)) ? sh[threadIdx.x] : 0.0f;
    if (wid == 0) {
        #pragma unroll
        for (int o = 16; o > 0; o >>= 1) v += __shfl_down_sync(0xffffffffu, v, o);
    }
    return v;   // valid in thread 0
}

// ---------------------------------------------------------------------------
// K1: transpose (+ fused relu(W)^2) -> grid spin barrier -> gather; entity blk.
// 1025 blocks @ 256 thr -> all co-resident (capacity >= 1184): spin is safe.
// ---------------------------------------------------------------------------
__global__ void __launch_bounds__(NTHR)
prep_k(const float* __restrict__ W,
       const float* __restrict__ E,
       const float* __restrict__ Sw,
       const float* __restrict__ Se,
       const int*   __restrict__ rowi,
       const int*   __restrict__ wi,
       const int*   __restrict__ ej,
       const int*   __restrict__ sj) {
    const int b = blockIdx.x;
    const int t = threadIdx.x;

    if (b < NTILES) {
        // ---- transpose one 32x32 tile of W; fuse relu^2 accumulation ----
        __shared__ float tile[32][33];
        const int tx = t & 31, ty = (t >> 5);     // 32 x 8
        const int tn = (b & 255) * 32;            // n base
        const int tk = (b >> 8) * 32;             // k base
        float wacc = 0.0f;
        #pragma unroll
        for (int i = 0; i < 32; i += 8) {
            float v = W[(size_t)(tk + ty + i) * NW + (tn + tx)];
            tile[ty + i][tx] = v;
            float r = fmaxf(v, 0.0f);
            wacc += r * r;
        }
        __syncthreads();
        #pragma unroll
        for (int i = 0; i < 32; i += 8)
            g_Wt[(size_t)(tn + ty + i) * KD + (tk + tx)] = tile[tx][ty + i];

        float wsum = block_reduce(wacc);
        if (t == 0) g_pwt[b] = wsum;

        // ---- signal + wait for all tiles ----
        __threadfence();
        if (t == 0) {
            atomicAdd(&g_tbar, 1);
            while (*(volatile int*)&g_tbar < NTILES) { }
        }
        __syncthreads();
        __threadfence();   // acquire g_Wt

        // ---- gather for group g = b (Wt rows L2-hot) ----
        __shared__ int idxs[MM];
        const int j = sj[b];
        if (t < MM) idxs[t] = wi[b * MM + t];
        __syncthreads();

        const int k    = t & (KD - 1);
        const int half = t >> 7;              // 0/1 split of m-range
        const float wjk = g_Wt[(size_t)j * KD + k];

        float acc = 0.0f;
        const int m0 = half * (MM / 2);
        #pragma unroll 8
        for (int m = m0; m < m0 + MM / 2; m++) {
            float d = wjk - g_Wt[(size_t)idxs[m] * KD + k];
            acc += d * d;
        }
        float swv = (t < MM) ? Sw[(size_t)j * NW + idxs[t]] : 0.0f;

        float d2 = block_reduce(acc);
        __syncthreads();
        float sw = block_reduce(swv);
        if (t == 0) g_sim[b] = sqrtf(d2) * sw;
    } else {
        // ---- entity term ----
        __shared__ int ejs[JJ];
        const int row_i = rowi[0];
        if (t < JJ) ejs[t] = ej[t];
        __syncthreads();
        float s_de = 0.0f;
        for (int i = t; i < JJ * KD; i += NTHR) {
            int jj = i >> 7;
            int kk = i & (KD - 1);
            float d = E[(size_t)row_i * KD + kk] - E[(size_t)ejs[jj] * KD + kk];
            s_de += d * d;
        }
        float s_se = (t < JJ) ? Se[(size_t)row_i * NE + ejs[t]] : 0.0f;
        float de = block_reduce(s_de);
        __syncthreads();
        float se = block_reduce(s_se);
        if (t == 0) { g_ent[0] = de; g_ent[1] = se; }
    }
}

// ---------------------------------------------------------------------------
// K2: pure HBM streaming reduce (PLAIN loads — the proven 81%-DRAM form)
//     + ticket compose. No W loop (done in prep).
// ---------------------------------------------------------------------------
__global__ void __launch_bounds__(NTHR, 8)
main_k(const float* __restrict__ actual,
       const float* __restrict__ pred,
       const float* __restrict__ E,
       const float* __restrict__ lamb,
       float* __restrict__ out) {
    const int b = blockIdx.x;
    const int t = threadIdx.x;
    const int tid    = b * NTHR + t;
    const int stride = NBLK * NTHR;

    const float4* a4 = (const float4*)actual;
    const float4* p4 = (const float4*)pred;
    const int n4 = (NE * NW) / 4;     // 8M

    float s0 = 0.f, s1 = 0.f, s2 = 0.f, s3 = 0.f;
    int i = tid;
    for (; i + 3 * stride < n4; i += 4 * stride) {
        float4 av0 = a4[i];
        float4 av1 = a4[i +     stride];
        float4 av2 = a4[i + 2 * stride];
        float4 av3 = a4[i + 3 * stride];
        float4 pv0 = p4[i];
        float4 pv1 = p4[i +     stride];
        float4 pv2 = p4[i + 2 * stride];
        float4 pv3 = p4[i + 3 * stride];
        float d;
        d = av0.x - pv0.x; s0 += d * d; d = av0.y - pv0.y; s0 += d * d;
        d = av0.z - pv0.z; s0 += d * d; d = av0.w - pv0.w; s0 += d * d;
        d = av1.x - pv1.x; s1 += d * d; d = av1.y - pv1.y; s1 += d * d;
        d = av1.z - pv1.z; s1 += d * d; d = av1.w - pv1.w; s1 += d * d;
        d = av2.x - pv2.x; s2 += d * d; d = av2.y - pv2.y; s2 += d * d;
        d = av2.z - pv2.z; s2 += d * d; d = av2.w - pv2.w; s2 += d * d;
        d = av3.x - pv3.x; s3 += d * d; d = av3.y - pv3.y; s3 += d * d;
        d = av3.z - pv3.z; s3 += d * d; d = av3.w - pv3.w; s3 += d * d;
    }
    for (; i < n4; i += stride) {
        float4 av = a4[i];
        float4 pv = p4[i];
        float d;
        d = av.x - pv.x; s0 += d * d; d = av.y - pv.y; s0 += d * d;
        d = av.z - pv.z; s0 += d * d; d = av.w - pv.w; s0 += d * d;
    }
    float s_r = (s0 + s1) + (s2 + s3);

    float s_e = 0.0f;
    {
        const float4* e4 = (const float4*)E;
        const int ne4 = (NE * KD) / 4;
        for (int q = tid; q < ne4; q += stride) {
            float4 v = e4[q];
            float r0 = fmaxf(v.x, 0.f), r1 = fmaxf(v.y, 0.f);
            float r2 = fmaxf(v.z, 0.f), r3 = fmaxf(v.w, 0.f);
            s_e += r0 * r0 + r1 * r1 + r2 * r2 + r3 * r3;
        }
    }

    float br = block_reduce(s_r);
    __syncthreads();
    float be = block_reduce(s_e);
    if (t == 0) {
        g_pr[b] = br;
        g_pe[b] = be;
    }

    // ---- Ticket: last block composes (fixed-order, deterministic) ----
    __shared__ int amLast;
    __threadfence();
    if (t == 0) {
        int r = atomicAdd(&g_done, 1);
        amLast = (r == NBLK - 1);
    }
    __syncthreads();

    if (amLast) {
        __threadfence();   // acquire all partials
        float sr = 0.f, sw = 0.f, se = 0.f, sim = 0.f;
        for (int q = t; q < NBLK; q += NTHR) {
            sr += g_pr[q];
            se += g_pe[q];
        }
        for (int q = t; q < NTILES; q += NTHR) sw += g_pwt[q];
        for (int q = t; q < GG; q += NTHR) sim += g_sim[q];

        float Sr  = block_reduce(sr);   __syncthreads();
        float Sw_ = block_reduce(sw);   __syncthreads();
        float Se_ = block_reduce(se);   __syncthreads();
        float Sim = block_reduce(sim);

        if (t == 0) {
            float recon = sqrtf(Sr);
            float param = sqrtf(Sw_) + sqrtf(Se_);
            float sim_p = Sim + sqrtf(g_ent[0]) * g_ent[1];
            out[0] = recon + lamb[0] * param + sim_p;
            g_done = 0;    // reset for next graph replay
            g_tbar = 0;    // reset K1's barrier (K2 strictly follows K1)
        }
    }
}

// ---------------------------------------------------------------------------
// Launch: two kernels, one stream.
// Inputs (metadata order):
//  0 actual  1 prediction  2 W  3 E  4 Sw  5 Se  6 lamb  7 row_ind
//  8 word_i_indices  9 entity_j_indices  10 sample_j_indices
// ---------------------------------------------------------------------------
extern "C" void kernel_launch(void* const* d_in, const int* in_sizes, int n_in,
                              void* d_out, int out_size) {
    const float* actual = (const float*)d_in[0];
    const float* pred   = (const float*)d_in[1];
    const float* W      = (const float*)d_in[2];
    const float* E      = (const float*)d_in[3];
    const float* Sw     = (const float*)d_in[4];
    const float* Se     = (const float*)d_in[5];
    const float* lamb   = (const float*)d_in[6];
    const int*   rowi   = (const int*)  d_in[7];
    const int*   wi     = (const int*)  d_in[8];
    const int*   ej     = (const int*)  d_in[9];
    const int*   sj     = (const int*)  d_in[10];
    float* out = (float*)d_out;

    prep_k<<<NTILES + 1, NTHR>>>(W, E, Sw, Se, rowi, wi, ej, sj);
    main_k<<<NBLK, NTHR>>>(actual, pred, E, lamb, out);
}

// round 9
// speedup vs baseline: 1.0042x; 1.0042x over previous
#include <cuda_runtime.h>
#include <math.h>

// Problem constants (fixed by the dataset)
#define NE 4096
#define NW 8192
#define KD 128
#define GG 1024
#define MM 64
#define JJ 256

#define NBLK 1184   // 148 SMs * 8 blocks (streaming kernel)
#define NTHR 256
#define NTILES 1024 // (8192/32)*(128/32) transpose tiles == GG

// Scratch (device globals — no runtime allocation allowed)
__device__ float g_Wt[NW * KD];    // transposed W (4 MB)
__device__ float g_pwt[NTILES];    // per-tile relu(W)^2 partials (from prep)
__device__ float g_pr[NBLK];
__device__ float g_pe[NBLK];
__device__ float g_sim[GG];
__device__ float g_ent[2];
__device__ int   g_tbar = 0;       // transpose-done counter (reset by K2 compose)
__device__ int   g_done = 0;       // K2 completion ticket  (reset by K2 compose)

__device__ __forceinline__ float block_reduce(float v) {
    __shared__ float sh[32];
    int lane = threadIdx.x & 31;
    int wid  = threadIdx.x >> 5;
    #pragma unroll
    for (int o = 16; o > 0; o >>= 1) v += __shfl_down_sync(0xffffffffu, v, o);
    __syncthreads();
    if (lane == 0) sh[wid] = v;
    __syncthreads();
    v = (threadIdx.x < (NTHR >> 5)) ? sh[threadIdx.x] : 0.0f;
    if (wid == 0) {
        #pragma unroll
        for (int o = 16; o > 0; o >>= 1) v += __shfl_down_sync(0xffffffffu, v, o);
    }
    return v;   // valid in thread 0
}

// ---------------------------------------------------------------------------
// K1: transpose (+ fused relu(W)^2) -> QUIET grid barrier -> gather; entity.
// 1025 blocks @ 256 thr -> all co-resident (capacity >= 1184): barrier safe.
// The barrier polls with __nanosleep backoff: no hot-spin power burn / L2
// hammering that would DVFS-throttle the following HBM kernel (R7/R8 lesson).
// ---------------------------------------------------------------------------
__global__ void __launch_bounds__(NTHR)
prep_k(const float* __restrict__ W,
       const float* __restrict__ E,
       const float* __restrict__ Sw,
       const float* __restrict__ Se,
       const int*   __restrict__ rowi,
       const int*   __restrict__ wi,
       const int*   __restrict__ ej,
       const int*   __restrict__ sj) {
    const int b = blockIdx.x;
    const int t = threadIdx.x;

    if (b < NTILES) {
        // ---- transpose one 32x32 tile of W; fuse relu^2 accumulation ----
        __shared__ float tile[32][33];
        const int tx = t & 31, ty = (t >> 5);     // 32 x 8
        const int tn = (b & 255) * 32;            // n base
        const int tk = (b >> 8) * 32;             // k base
        float wacc = 0.0f;
        #pragma unroll
        for (int i = 0; i < 32; i += 8) {
            float v = W[(size_t)(tk + ty + i) * NW + (tn + tx)];
            tile[ty + i][tx] = v;
            float r = fmaxf(v, 0.0f);
            wacc += r * r;
        }
        __syncthreads();
        #pragma unroll
        for (int i = 0; i < 32; i += 8)
            g_Wt[(size_t)(tn + ty + i) * KD + (tk + tx)] = tile[tx][ty + i];

        float wsum = block_reduce(wacc);
        if (t == 0) g_pwt[b] = wsum;

        // ---- quiet barrier: signal, then poll with nanosleep backoff ----
        __threadfence();
        if (t == 0) {
            atomicAdd(&g_tbar, 1);
            if (*(volatile int*)&g_tbar < NTILES) {
                do {
                    __nanosleep(256);
                } while (*(volatile int*)&g_tbar < NTILES);
            }
        }
        __syncthreads();
        __threadfence();   // acquire g_Wt

        // ---- gather for group g = b (Wt rows L2-hot) ----
        __shared__ int idxs[MM];
        const int j = sj[b];
        if (t < MM) idxs[t] = wi[b * MM + t];
        __syncthreads();

        const int k    = t & (KD - 1);
        const int half = t >> 7;              // 0/1 split of m-range
        const float wjk = g_Wt[(size_t)j * KD + k];

        float acc = 0.0f;
        const int m0 = half * (MM / 2);
        #pragma unroll 8
        for (int m = m0; m < m0 + MM / 2; m++) {
            float d = wjk - g_Wt[(size_t)idxs[m] * KD + k];
            acc += d * d;
        }
        float swv = (t < MM) ? Sw[(size_t)j * NW + idxs[t]] : 0.0f;

        float d2 = block_reduce(acc);
        __syncthreads();
        float sw = block_reduce(swv);
        if (t == 0) g_sim[b] = sqrtf(d2) * sw;
    } else {
        // ---- entity term ----
        __shared__ int ejs[JJ];
        const int row_i = rowi[0];
        if (t < JJ) ejs[t] = ej[t];
        __syncthreads();
        float s_de = 0.0f;
        for (int i = t; i < JJ * KD; i += NTHR) {
            int jj = i >> 7;
            int kk = i & (KD - 1);
            float d = E[(size_t)row_i * KD + kk] - E[(size_t)ejs[jj] * KD + kk];
            s_de += d * d;
        }
        float s_se = (t < JJ) ? Se[(size_t)row_i * NE + ejs[t]] : 0.0f;
        float de = block_reduce(s_de);
        __syncthreads();
        float se = block_reduce(s_se);
        if (t == 0) { g_ent[0] = de; g_ent[1] = se; }
    }
}

// ---------------------------------------------------------------------------
// K2: pure HBM streaming reduce (plain float4 loads, the proven form)
//     + ticket compose. No pre-phase, no W loop (done in prep).
// ---------------------------------------------------------------------------
__global__ void __launch_bounds__(NTHR, 8)
main_k(const float* __restrict__ actual,
       const float* __restrict__ pred,
       const float* __restrict__ E,
       const float* __restrict__ lamb,
       float* __restrict__ out) {
    const int b = blockIdx.x;
    const int t = threadIdx.x;
    const int tid    = b * NTHR + t;
    const int stride = NBLK * NTHR;

    const float4* a4 = (const float4*)actual;
    const float4* p4 = (const float4*)pred;
    const int n4 = (NE * NW) / 4;     // 8M

    float s0 = 0.f, s1 = 0.f, s2 = 0.f, s3 = 0.f;
    int i = tid;
    for (; i + 3 * stride < n4; i += 4 * stride) {
        float4 av0 = a4[i];
        float4 av1 = a4[i +     stride];
        float4 av2 = a4[i + 2 * stride];
        float4 av3 = a4[i + 3 * stride];
        float4 pv0 = p4[i];
        float4 pv1 = p4[i +     stride];
        float4 pv2 = p4[i + 2 * stride];
        float4 pv3 = p4[i + 3 * stride];
        float d;
        d = av0.x - pv0.x; s0 += d * d; d = av0.y - pv0.y; s0 += d * d;
        d = av0.z - pv0.z; s0 += d * d; d = av0.w - pv0.w; s0 += d * d;
        d = av1.x - pv1.x; s1 += d * d; d = av1.y - pv1.y; s1 += d * d;
        d = av1.z - pv1.z; s1 += d * d; d = av1.w - pv1.w; s1 += d * d;
        d = av2.x - pv2.x; s2 += d * d; d = av2.y - pv2.y; s2 += d * d;
        d = av2.z - pv2.z; s2 += d * d; d = av2.w - pv2.w; s2 += d * d;
        d = av3.x - pv3.x; s3 += d * d; d = av3.y - pv3.y; s3 += d * d;
        d = av3.z - pv3.z; s3 += d * d; d = av3.w - pv3.w; s3 += d * d;
    }
    for (; i < n4; i += stride) {
        float4 av = a4[i];
        float4 pv = p4[i];
        float d;
        d = av.x - pv.x; s0 += d * d; d = av.y - pv.y; s0 += d * d;
        d = av.z - pv.z; s0 += d * d; d = av.w - pv.w; s0 += d * d;
    }
    float s_r = (s0 + s1) + (s2 + s3);

    float s_e = 0.0f;
    {
        const float4* e4 = (const float4*)E;
        const int ne4 = (NE * KD) / 4;
        for (int q = tid; q < ne4; q += stride) {
            float4 v = e4[q];
            float r0 = fmaxf(v.x, 0.f), r1 = fmaxf(v.y, 0.f);
            float r2 = fmaxf(v.z, 0.f), r3 = fmaxf(v.w, 0.f);
            s_e += r0 * r0 + r1 * r1 + r2 * r2 + r3 * r3;
        }
    }

    float br = block_reduce(s_r);
    __syncthreads();
    float be = block_reduce(s_e);
    if (t == 0) {
        g_pr[b] = br;
        g_pe[b] = be;
    }

    // ---- Ticket: last block composes (fixed-order, deterministic) ----
    __shared__ int amLast;
    __threadfence();
    if (t == 0) {
        int r = atomicAdd(&g_done, 1);
        amLast = (r == NBLK - 1);
    }
    __syncthreads();

    if (amLast) {
        __threadfence();   // acquire all partials
        float sr = 0.f, sw = 0.f, se = 0.f, sim = 0.f;
        for (int q = t; q < NBLK; q += NTHR) {
            sr += g_pr[q];
            se += g_pe[q];
        }
        for (int q = t; q < NTILES; q += NTHR) sw += g_pwt[q];
        for (int q = t; q < GG; q += NTHR) sim += g_sim[q];

        float Sr  = block_reduce(sr);   __syncthreads();
        float Sw_ = block_reduce(sw);   __syncthreads();
        float Se_ = block_reduce(se);   __syncthreads();
        float Sim = block_reduce(sim);

        if (t == 0) {
            float recon = sqrtf(Sr);
            float param = sqrtf(Sw_) + sqrtf(Se_);
            float sim_p = Sim + sqrtf(g_ent[0]) * g_ent[1];
            out[0] = recon + lamb[0] * param + sim_p;
            g_done = 0;    // reset for next graph replay
            g_tbar = 0;    // reset K1's barrier (K2 strictly follows K1)
        }
    }
}

// ---------------------------------------------------------------------------
// Launch: two kernels, one stream.
// Inputs (metadata order):
//  0 actual  1 prediction  2 W  3 E  4 Sw  5 Se  6 lamb  7 row_ind
//  8 word_i_indices  9 entity_j_indices  10 sample_j_indices
// ---------------------------------------------------------------------------
extern "C" void kernel_launch(void* const* d_in, const int* in_sizes, int n_in,
                              void* d_out, int out_size) {
    const float* actual = (const float*)d_in[0];
    const float* pred   = (const float*)d_in[1];
    const float* W      = (const float*)d_in[2];
    const float* E      = (const float*)d_in[3];
    const float* Sw     = (const float*)d_in[4];
    const float* Se     = (const float*)d_in[5];
    const float* lamb   = (const float*)d_in[6];
    const int*   rowi   = (const int*)  d_in[7];
    const int*   wi     = (const int*)  d_in[8];
    const int*   ej     = (const int*)  d_in[9];
    const int*   sj     = (const int*)  d_in[10];
    float* out = (float*)d_out;

    prep_k<<<NTILES + 1, NTHR>>>(W, E, Sw, Se, rowi, wi, ej, sj);
    main_k<<<NBLK, NTHR>>>(actual, pred, E, lamb, out);
}

// round 10
// speedup vs baseline: 1.0220x; 1.0177x over previous
#include <cuda_runtime.h>
#include <math.h>

// Problem constants (fixed by the dataset)
#define NE 4096
#define NW 8192
#define KD 128
#define GG 1024
#define MM 64
#define JJ 256

#define NBLK 1184   // 148 SMs * 8 blocks (streaming kernel)
#define NTHR 256
#define NTILES 1024 // (8192/32)*(128/32) transpose tiles == GG

// Scratch (device globals — no runtime allocation allowed)
__device__ float g_Wt[NW * KD];    // transposed W (4 MB)
__device__ float g_pwt[NTILES];    // per-tile relu(W)^2 partials (K1)
__device__ float g_pr[NBLK];       // per-block (a-p)^2 partials (K2)
__device__ float g_pe[NBLK];       // per-block relu(E)^2 partials (K2)
__device__ float g_sim[GG];        // per-group word sim term (K3)
__device__ float g_ent[2];         // entity term (K1)
__device__ int   g_done = 0;       // K3 gather ticket (reset by compose)

__device__ __forceinline__ float block_reduce(float v) {
    __shared__ float sh[32];
    int lane = threadIdx.x & 31;
    int wid  = threadIdx.x >> 5;
    #pragma unroll
    for (int o = 16; o > 0; o >>= 1) v += __shfl_down_sync(0xffffffffu, v, o);
    __syncthreads();
    if (lane == 0) sh[wid] = v;
    __syncthreads();
    v = (threadIdx.x < (NTHR >> 5)) ? sh[threadIdx.x] : 0.0f;
    if (wid == 0) {
        #pragma unroll
        for (int o = 16; o > 0; o >>= 1) v += __shfl_down_sync(0xffffffffu, v, o);
    }
    return v;   // valid in thread 0
}

// ---------------------------------------------------------------------------
// K1: transpose W (+ fused relu(W)^2 partials) + entity term. No barrier.
// ---------------------------------------------------------------------------
__global__ void __launch_bounds__(NTHR)
prep_k(const float* __restrict__ W,
       const float* __restrict__ E,
       const float* __restrict__ Se,
       const int*   __restrict__ rowi,
       const int*   __restrict__ ej) {
    const int b = blockIdx.x;
    const int t = threadIdx.x;

    if (b < NTILES) {
        __shared__ float tile[32][33];
        const int tx = t & 31, ty = (t >> 5);     // 32 x 8
        const int tn = (b & 255) * 32;            // n base
        const int tk = (b >> 8) * 32;             // k base
        float wacc = 0.0f;
        #pragma unroll
        for (int i = 0; i < 32; i += 8) {
            float v = W[(size_t)(tk + ty + i) * NW + (tn + tx)];
            tile[ty + i][tx] = v;
            float r = fmaxf(v, 0.0f);
            wacc += r * r;
        }
        __syncthreads();
        #pragma unroll
        for (int i = 0; i < 32; i += 8)
            g_Wt[(size_t)(tn + ty + i) * KD + (tk + tx)] = tile[tx][ty + i];

        float wsum = block_reduce(wacc);
        if (t == 0) g_pwt[b] = wsum;
    } else {
        // ---- entity term ----
        __shared__ int ejs[JJ];
        const int row_i = rowi[0];
        if (t < JJ) ejs[t] = ej[t];
        __syncthreads();
        float s_de = 0.0f;
        for (int i = t; i < JJ * KD; i += NTHR) {
            int jj = i >> 7;
            int kk = i & (KD - 1);
            float d = E[(size_t)row_i * KD + kk] - E[(size_t)ejs[jj] * KD + kk];
            s_de += d * d;
        }
        float s_se = (t < JJ) ? Se[(size_t)row_i * NE + ejs[t]] : 0.0f;
        float de = block_reduce(s_de);
        __syncthreads();
        float se = block_reduce(s_se);
        if (t == 0) { g_ent[0] = de; g_ent[1] = se; }
    }
}

// ---------------------------------------------------------------------------
// K2: PURE HBM streaming reduce — no pre-phase, no compose tail.
// Fires the PDL trigger at block start so K3 stages and fills as K2 drains.
// ---------------------------------------------------------------------------
__global__ void __launch_bounds__(NTHR, 8)
stream_k(const float* __restrict__ actual,
         const float* __restrict__ pred,
         const float* __restrict__ E) {
    asm volatile("griddepcontrol.launch_dependents;");

    const int b = blockIdx.x;
    const int t = threadIdx.x;
    const int tid    = b * NTHR + t;
    const int stride = NBLK * NTHR;

    const float4* a4 = (const float4*)actual;
    const float4* p4 = (const float4*)pred;
    const int n4 = (NE * NW) / 4;     // 8M

    float s0 = 0.f, s1 = 0.f, s2 = 0.f, s3 = 0.f;
    int i = tid;
    for (; i + 3 * stride < n4; i += 4 * stride) {
        float4 av0 = a4[i];
        float4 av1 = a4[i +     stride];
        float4 av2 = a4[i + 2 * stride];
        float4 av3 = a4[i + 3 * stride];
        float4 pv0 = p4[i];
        float4 pv1 = p4[i +     stride];
        float4 pv2 = p4[i + 2 * stride];
        float4 pv3 = p4[i + 3 * stride];
        float d;
        d = av0.x - pv0.x; s0 += d * d; d = av0.y - pv0.y; s0 += d * d;
        d = av0.z - pv0.z; s0 += d * d; d = av0.w - pv0.w; s0 += d * d;
        d = av1.x - pv1.x; s1 += d * d; d = av1.y - pv1.y; s1 += d * d;
        d = av1.z - pv1.z; s1 += d * d; d = av1.w - pv1.w; s1 += d * d;
        d = av2.x - pv2.x; s2 += d * d; d = av2.y - pv2.y; s2 += d * d;
        d = av2.z - pv2.z; s2 += d * d; d = av2.w - pv2.w; s2 += d * d;
        d = av3.x - pv3.x; s3 += d * d; d = av3.y - pv3.y; s3 += d * d;
        d = av3.z - pv3.z; s3 += d * d; d = av3.w - pv3.w; s3 += d * d;
    }
    for (; i < n4; i += stride) {
        float4 av = a4[i];
        float4 pv = p4[i];
        float d;
        d = av.x - pv.x; s0 += d * d; d = av.y - pv.y; s0 += d * d;
        d = av.z - pv.z; s0 += d * d; d = av.w - pv.w; s0 += d * d;
    }
    float s_r = (s0 + s1) + (s2 + s3);

    float s_e = 0.0f;
    {
        const float4* e4 = (const float4*)E;
        const int ne4 = (NE * KD) / 4;
        for (int q = tid; q < ne4; q += stride) {
            float4 v = e4[q];
            float r0 = fmaxf(v.x, 0.f), r1 = fmaxf(v.y, 0.f);
            float r2 = fmaxf(v.z, 0.f), r3 = fmaxf(v.w, 0.f);
            s_e += r0 * r0 + r1 * r1 + r2 * r2 + r3 * r3;
        }
    }

    float br = block_reduce(s_r);
    __syncthreads();
    float be = block_reduce(s_e);
    if (t == 0) {
        g_pr[b] = br;
        g_pe[b] = be;
    }
}

// ---------------------------------------------------------------------------
// K3 (PDL-launched): gather per group; ticket-elected last block waits for
// K2 completion (griddepcontrol.wait) and composes the final scalar.
// Gather blocks overlap K2's drain — they only read K1 outputs + Sw/wi/sj.
// ---------------------------------------------------------------------------
__global__ void __launch_bounds__(NTHR)
finish_k(const float* __restrict__ Sw,
         const float* __restrict__ lamb,
         const int*   __restrict__ wi,
         const int*   __restrict__ sj,
         float* __restrict__ out) {
    const int b = blockIdx.x;     // 0..GG-1
    const int t = threadIdx.x;

    // ---- gather for group g = b ----
    __shared__ int idxs[MM];
    const int j = sj[b];
    if (t < MM) idxs[t] = wi[b * MM + t];
    __syncthreads();

    const int k    = t & (KD - 1);
    const int half = t >> 7;              // 0/1 split of m-range
    float swv = (t < MM) ? Sw[(size_t)j * NW + idxs[t]] : 0.0f;  // issue early (DRAM)
    const float wjk = g_Wt[(size_t)j * KD + k];

    float acc = 0.0f;
    const int m0 = half * (MM / 2);
    #pragma unroll 8
    for (int m = m0; m < m0 + MM / 2; m++) {
        float d = wjk - g_Wt[(size_t)idxs[m] * KD + k];
        acc += d * d;
    }

    float d2 = block_reduce(acc);
    __syncthreads();
    float sw = block_reduce(swv);
    if (t == 0) g_sim[b] = sqrtf(d2) * sw;

    // ---- ticket: last gather block composes ----
    __shared__ int amLast;
    __threadfence();
    if (t == 0) {
        int r = atomicAdd(&g_done, 1);
        amLast = (r == GG - 1);
    }
    __syncthreads();

    if (amLast) {
        // Wait for K2 grid completion + memory visibility (g_pr/g_pe).
        asm volatile("griddepcontrol.wait;");
        __threadfence();

        float sr = 0.f, sw2 = 0.f, se = 0.f, sim = 0.f;
        for (int q = t; q < NBLK; q += NTHR) {
            sr += g_pr[q];
            se += g_pe[q];
        }
        for (int q = t; q < NTILES; q += NTHR) sw2 += g_pwt[q];
        for (int q = t; q < GG; q += NTHR) sim += g_sim[q];

        float Sr  = block_reduce(sr);   __syncthreads();
        float Sw_ = block_reduce(sw2);  __syncthreads();
        float Se_ = block_reduce(se);   __syncthreads();
        float Sim = block_reduce(sim);

        if (t == 0) {
            float recon = sqrtf(Sr);
            float param = sqrtf(Sw_) + sqrtf(Se_);
            float sim_p = Sim + sqrtf(g_ent[0]) * g_ent[1];
            out[0] = recon + lamb[0] * param + sim_p;
            g_done = 0;    // reset for next graph replay
        }
    }
}

// ---------------------------------------------------------------------------
// Launch: K1 -> K2 (normal order), K3 with programmatic-stream-serialization
// so its gather blocks launch while K2 drains; compose gated by
// griddepcontrol.wait on K2.
// Inputs (metadata order):
//  0 actual  1 prediction  2 W  3 E  4 Sw  5 Se  6 lamb  7 row_ind
//  8 word_i_indices  9 entity_j_indices  10 sample_j_indices
// ---------------------------------------------------------------------------
extern "C" void kernel_launch(void* const* d_in, const int* in_sizes, int n_in,
                              void* d_out, int out_size) {
    const float* actual = (const float*)d_in[0];
    const float* pred   = (const float*)d_in[1];
    const float* W      = (const float*)d_in[2];
    const float* E      = (const float*)d_in[3];
    const float* Sw     = (const float*)d_in[4];
    const float* Se     = (const float*)d_in[5];
    const float* lamb   = (const float*)d_in[6];
    const int*   rowi   = (const int*)  d_in[7];
    const int*   wi     = (const int*)  d_in[8];
    const int*   ej     = (const int*)  d_in[9];
    const int*   sj     = (const int*)  d_in[10];
    float* out = (float*)d_out;

    prep_k<<<NTILES + 1, NTHR>>>(W, E, Se, rowi, ej);
    stream_k<<<NBLK, NTHR>>>(actual, pred, E);

    // K3: PDL launch
    {
        cudaLaunchConfig_t cfg = {};
        cfg.gridDim  = dim3(GG, 1, 1);
        cfg.blockDim = dim3(NTHR, 1, 1);
        cfg.dynamicSmemBytes = 0;
        cfg.stream = (cudaStream_t)0;
        cudaLaunchAttribute attrs[1];
        attrs[0].id = cudaLaunchAttributeProgrammaticStreamSerialization;
        attrs[0].val.programmaticStreamSerializationAllowed = 1;
        cfg.attrs = attrs;
        cfg.numAttrs = 1;
        cudaLaunchKernelEx(&cfg, finish_k, Sw, lamb, wi, sj, out);
    }
}

// round 11
// speedup vs baseline: 1.0988x; 1.0751x over previous
#include <cuda_runtime.h>
#include <math.h>

// Problem constants (fixed by the dataset)
#define NE 4096
#define NW 8192
#define KD 128
#define GG 1024
#define MM 64
#define JJ 256

#define NBLK 1184   // 148 SMs * 8 blocks (streaming kernel)
#define NTHR 256
#define NTILES 1024 // (8192/32)*(128/32) transpose tiles == GG

// Scratch (device globals — no runtime allocation allowed)
__device__ float g_Wt[NW * KD];    // transposed W (4 MB)
__device__ float g_pwt[NTILES];    // per-tile relu(W)^2 partials (K1)
__device__ float g_pr[NBLK];       // per-block (a-p)^2 partials (K2)
__device__ float g_pe[NBLK];       // per-block relu(E)^2 partials (K2)
__device__ float g_sim[GG];        // per-group word sim term (K3)
__device__ float g_ent[2];         // entity term (K1)
__device__ int   g_done = 0;       // K3 gather ticket (reset by compose)

__device__ __forceinline__ float block_reduce(float v) {
    __shared__ float sh[32];
    int lane = threadIdx.x & 31;
    int wid  = threadIdx.x >> 5;
    #pragma unroll
    for (int o = 16; o > 0; o >>= 1) v += __shfl_down_sync(0xffffffffu, v, o);
    __syncthreads();
    if (lane == 0) sh[wid] = v;
    __syncthreads();
    v = (threadIdx.x < (NTHR >> 5)) ? sh[threadIdx.x] : 0.0f;
    if (wid == 0) {
        #pragma unroll
        for (int o = 16; o > 0; o >>= 1) v += __shfl_down_sync(0xffffffffu, v, o);
    }
    return v;   // valid in thread 0
}

// ---------------------------------------------------------------------------
// K1: transpose W (+ fused relu(W)^2) + entity term.
// Issues the PDL trigger at block start: K2's DRAM-bound blocks flood in as
// these tiny issue-bound blocks retire -> prep cost overlaps K2 (R10 lesson:
// prep alone is 17us of issue-bound work, 3% DRAM -- complementary to K2).
// ---------------------------------------------------------------------------
__global__ void __launch_bounds__(NTHR)
prep_k(const float* __restrict__ W,
       const float* __restrict__ E,
       const float* __restrict__ Se,
       const int*   __restrict__ rowi,
       const int*   __restrict__ ej) {
    asm volatile("griddepcontrol.launch_dependents;");

    const int b = blockIdx.x;
    const int t = threadIdx.x;

    if (b < NTILES) {
        __shared__ float tile[32][33];
        const int tx = t & 31, ty = (t >> 5);     // 32 x 8
        const int tn = (b & 255) * 32;            // n base
        const int tk = (b >> 8) * 32;             // k base
        float wacc = 0.0f;
        #pragma unroll
        for (int i = 0; i < 32; i += 8) {
            float v = W[(size_t)(tk + ty + i) * NW + (tn + tx)];
            tile[ty + i][tx] = v;
            float r = fmaxf(v, 0.0f);
            wacc += r * r;
        }
        __syncthreads();
        #pragma unroll
        for (int i = 0; i < 32; i += 8)
            g_Wt[(size_t)(tn + ty + i) * KD + (tk + tx)] = tile[tx][ty + i];

        float wsum = block_reduce(wacc);
        if (t == 0) g_pwt[b] = wsum;
    } else {
        // ---- entity term ----
        __shared__ int ejs[JJ];
        const int row_i = rowi[0];
        if (t < JJ) ejs[t] = ej[t];
        __syncthreads();
        float s_de = 0.0f;
        for (int i = t; i < JJ * KD; i += NTHR) {
            int jj = i >> 7;
            int kk = i & (KD - 1);
            float d = E[(size_t)row_i * KD + kk] - E[(size_t)ejs[jj] * KD + kk];
            s_de += d * d;
        }
        float s_se = (t < JJ) ? Se[(size_t)row_i * NE + ejs[t]] : 0.0f;
        float de = block_reduce(s_de);
        __syncthreads();
        float se = block_reduce(s_se);
        if (t == 0) { g_ent[0] = de; g_ent[1] = se; }
    }
}

// ---------------------------------------------------------------------------
// K2: PURE HBM streaming reduce. PDL-dependent on K1 (starts as K1 drains;
// does NOT read K1 outputs, so no wait needed). Triggers K3.
// ---------------------------------------------------------------------------
__global__ void __launch_bounds__(NTHR, 8)
stream_k(const float* __restrict__ actual,
         const float* __restrict__ pred,
         const float* __restrict__ E) {
    asm volatile("griddepcontrol.launch_dependents;");

    const int b = blockIdx.x;
    const int t = threadIdx.x;
    const int tid    = b * NTHR + t;
    const int stride = NBLK * NTHR;

    const float4* a4 = (const float4*)actual;
    const float4* p4 = (const float4*)pred;
    const int n4 = (NE * NW) / 4;     // 8M

    float s0 = 0.f, s1 = 0.f, s2 = 0.f, s3 = 0.f;
    int i = tid;
    for (; i + 3 * stride < n4; i += 4 * stride) {
        float4 av0 = a4[i];
        float4 av1 = a4[i +     stride];
        float4 av2 = a4[i + 2 * stride];
        float4 av3 = a4[i + 3 * stride];
        float4 pv0 = p4[i];
        float4 pv1 = p4[i +     stride];
        float4 pv2 = p4[i + 2 * stride];
        float4 pv3 = p4[i + 3 * stride];
        float d;
        d = av0.x - pv0.x; s0 += d * d; d = av0.y - pv0.y; s0 += d * d;
        d = av0.z - pv0.z; s0 += d * d; d = av0.w - pv0.w; s0 += d * d;
        d = av1.x - pv1.x; s1 += d * d; d = av1.y - pv1.y; s1 += d * d;
        d = av1.z - pv1.z; s1 += d * d; d = av1.w - pv1.w; s1 += d * d;
        d = av2.x - pv2.x; s2 += d * d; d = av2.y - pv2.y; s2 += d * d;
        d = av2.z - pv2.z; s2 += d * d; d = av2.w - pv2.w; s2 += d * d;
        d = av3.x - pv3.x; s3 += d * d; d = av3.y - pv3.y; s3 += d * d;
        d = av3.z - pv3.z; s3 += d * d; d = av3.w - pv3.w; s3 += d * d;
    }
    for (; i < n4; i += stride) {
        float4 av = a4[i];
        float4 pv = p4[i];
        float d;
        d = av.x - pv.x; s0 += d * d; d = av.y - pv.y; s0 += d * d;
        d = av.z - pv.z; s0 += d * d; d = av.w - pv.w; s0 += d * d;
    }
    float s_r = (s0 + s1) + (s2 + s3);

    float s_e = 0.0f;
    {
        const float4* e4 = (const float4*)E;
        const int ne4 = (NE * KD) / 4;
        for (int q = tid; q < ne4; q += stride) {
            float4 v = e4[q];
            float r0 = fmaxf(v.x, 0.f), r1 = fmaxf(v.y, 0.f);
            float r2 = fmaxf(v.z, 0.f), r3 = fmaxf(v.w, 0.f);
            s_e += r0 * r0 + r1 * r1 + r2 * r2 + r3 * r3;
        }
    }

    float br = block_reduce(s_r);
    __syncthreads();
    float be = block_reduce(s_e);
    if (t == 0) {
        g_pr[b] = br;
        g_pe[b] = be;
    }
}

// ---------------------------------------------------------------------------
// K3 (PDL-dependent on K2): wait for K2 completion (stream-ordered, so K1 is
// also complete -> g_Wt valid), then gather per group; last block composes.
// ---------------------------------------------------------------------------
__global__ void __launch_bounds__(NTHR)
finish_k(const float* __restrict__ Sw,
         const float* __restrict__ lamb,
         const int*   __restrict__ wi,
         const int*   __restrict__ sj,
         float* __restrict__ out) {
    // Wait for predecessor grid completion + memory visibility. Stream
    // ordering guarantees K1 completed before K2 completed, so g_Wt, g_pwt,
    // g_ent, g_pr, g_pe are ALL valid after this.
    asm volatile("griddepcontrol.wait;");

    const int b = blockIdx.x;     // 0..GG-1
    const int t = threadIdx.x;

    // ---- gather for group g = b ----
    __shared__ int idxs[MM];
    const int j = sj[b];
    if (t < MM) idxs[t] = wi[b * MM + t];
    __syncthreads();

    const int k    = t & (KD - 1);
    const int half = t >> 7;              // 0/1 split of m-range
    float swv = (t < MM) ? Sw[(size_t)j * NW + idxs[t]] : 0.0f;  // issue early
    const float wjk = g_Wt[(size_t)j * KD + k];

    float acc = 0.0f;
    const int m0 = half * (MM / 2);
    #pragma unroll 8
    for (int m = m0; m < m0 + MM / 2; m++) {
        float d = wjk - g_Wt[(size_t)idxs[m] * KD + k];
        acc += d * d;
    }

    float d2 = block_reduce(acc);
    __syncthreads();
    float sw = block_reduce(swv);
    if (t == 0) g_sim[b] = sqrtf(d2) * sw;

    // ---- ticket: last gather block composes ----
    __shared__ int amLast;
    __threadfence();
    if (t == 0) {
        int r = atomicAdd(&g_done, 1);
        amLast = (r == GG - 1);
    }
    __syncthreads();

    if (amLast) {
        __threadfence();   // acquire g_sim from other blocks

        float sr = 0.f, sw2 = 0.f, se = 0.f, sim = 0.f;
        for (int q = t; q < NBLK; q += NTHR) {
            sr += g_pr[q];
            se += g_pe[q];
        }
        for (int q = t; q < NTILES; q += NTHR) sw2 += g_pwt[q];
        for (int q = t; q < GG; q += NTHR) sim += g_sim[q];

        float Sr  = block_reduce(sr);   __syncthreads();
        float Sw_ = block_reduce(sw2);  __syncthreads();
        float Se_ = block_reduce(se);   __syncthreads();
        float Sim = block_reduce(sim);

        if (t == 0) {
            float recon = sqrtf(Sr);
            float param = sqrtf(Sw_) + sqrtf(Se_);
            float sim_p = Sim + sqrtf(g_ent[0]) * g_ent[1];
            out[0] = recon + lamb[0] * param + sim_p;
            g_done = 0;    // reset for next graph replay
        }
    }
}

// ---------------------------------------------------------------------------
// Launch: PDL chain K1 -> K2 -> K3. K2 and K3 opt in via
// ProgrammaticStreamSerialization; triggers fire at predecessor block start.
// Inputs (metadata order):
//  0 actual  1 prediction  2 W  3 E  4 Sw  5 Se  6 lamb  7 row_ind
//  8 word_i_indices  9 entity_j_indices  10 sample_j_indices
// ---------------------------------------------------------------------------
extern "C" void kernel_launch(void* const* d_in, const int* in_sizes, int n_in,
                              void* d_out, int out_size) {
    const float* actual = (const float*)d_in[0];
    const float* pred   = (const float*)d_in[1];
    const float* W      = (const float*)d_in[2];
    const float* E      = (const float*)d_in[3];
    const float* Sw     = (const float*)d_in[4];
    const float* Se     = (const float*)d_in[5];
    const float* lamb   = (const float*)d_in[6];
    const int*   rowi   = (const int*)  d_in[7];
    const int*   wi     = (const int*)  d_in[8];
    const int*   ej     = (const int*)  d_in[9];
    const int*   sj     = (const int*)  d_in[10];
    float* out = (float*)d_out;

    // K1: normal launch
    prep_k<<<NTILES + 1, NTHR>>>(W, E, Se, rowi, ej);

    cudaLaunchAttribute pdl[1];
    pdl[0].id = cudaLaunchAttributeProgrammaticStreamSerialization;
    pdl[0].val.programmaticStreamSerializationAllowed = 1;

    // K2: PDL-dependent on K1 (overlaps K1's drain; reads only a/p/E)
    {
        cudaLaunchConfig_t cfg = {};
        cfg.gridDim  = dim3(NBLK, 1, 1);
        cfg.blockDim = dim3(NTHR, 1, 1);
        cfg.dynamicSmemBytes = 0;
        cfg.stream = (cudaStream_t)0;
        cfg.attrs = pdl;
        cfg.numAttrs = 1;
        cudaLaunchKernelEx(&cfg, stream_k, actual, pred, E);
    }

    // K3: PDL-dependent on K2; waits in-kernel before touching K1/K2 outputs
    {
        cudaLaunchConfig_t cfg = {};
        cfg.gridDim  = dim3(GG, 1, 1);
        cfg.blockDim = dim3(NTHR, 1, 1);
        cfg.dynamicSmemBytes = 0;
        cfg.stream = (cudaStream_t)0;
        cfg.attrs = pdl;
        cfg.numAttrs = 1;
        cudaLaunchKernelEx(&cfg, finish_k, Sw, lamb, wi, sj, out);
    }
}